// round 1
// baseline (speedup 1.0000x reference)
#include <cuda_runtime.h>

#define EMB 128
#define MAXNODES 100000
#define ETILE 32
#define OROWS 8

// Scratch (device globals: no allocations allowed in kernel_launch)
__device__ __align__(128) float g_Lp[MAXNODES * EMB];     // left_proj
__device__ __align__(128) float g_Rp[MAXNODES * EMB];     // right_proj
__device__ __align__(128) float g_conv[MAXNODES * EMB];   // scatter accumulator
__device__ int g_is64;

// ---------------------------------------------------------------------------
// Detect whether edge_indices buffer is int64 or int32 (JAX x64-off pitfall).
// If the data is int32, interpreting pairs as int64 yields values >= 2^32
// whenever the high word (itself a random index in [0,1e5)) is nonzero.
// ---------------------------------------------------------------------------
__global__ void detect_idx_kernel(const long long* __restrict__ e, int n64_safe) {
    if (blockIdx.x == 0 && threadIdx.x == 0) {
        int m = n64_safe < 64 ? n64_safe : 64;
        int ok = 1;
        for (int i = 0; i < m; i++) {
            long long v = e[i];
            if (v < 0 || v >= (1LL << 31)) { ok = 0; break; }
        }
        g_is64 = ok;
    }
}

__global__ void zero_conv_kernel(int n4) {
    int i = blockIdx.x * blockDim.x + threadIdx.x;
    if (i < n4) ((float4*)g_conv)[i] = make_float4(0.f, 0.f, 0.f, 0.f);
}

// ---------------------------------------------------------------------------
// out[m, j] = sum_k A[m,k] * W[j,k] + b[j]      (A: [n_rows,128], W: [128,128])
// 128 threads, thread j owns output column j; 64 rows per block, 4 at a time.
// ---------------------------------------------------------------------------
__global__ __launch_bounds__(128) void proj_kernel(
    const float* __restrict__ A, const float* __restrict__ W,
    const float* __restrict__ b, float* __restrict__ out, int n_rows)
{
    __shared__ __align__(16) float As[4][EMB];
    const int j = threadIdx.x;
    const int row0 = blockIdx.x * 64;
    const float bj = b ? b[j] : 0.0f;
    const float4* __restrict__ W4 = (const float4*)(W + j * EMB);

    for (int rt = 0; rt < 64; rt += 4) {
        const int rbase = row0 + rt;
        const int rr = threadIdx.x >> 5;
        const int c4 = threadIdx.x & 31;
        float4 v = make_float4(0.f, 0.f, 0.f, 0.f);
        if (rbase + rr < n_rows)
            v = ((const float4*)(A + (size_t)(rbase + rr) * EMB))[c4];
        __syncthreads();
        ((float4*)As[rr])[c4] = v;
        __syncthreads();

        float a0 = bj, a1 = bj, a2 = bj, a3 = bj;
#pragma unroll
        for (int k4 = 0; k4 < 32; k4++) {
            const float4 w = W4[k4];
            float4 x;
            x = ((const float4*)As[0])[k4];
            a0 = fmaf(w.x, x.x, a0); a0 = fmaf(w.y, x.y, a0);
            a0 = fmaf(w.z, x.z, a0); a0 = fmaf(w.w, x.w, a0);
            x = ((const float4*)As[1])[k4];
            a1 = fmaf(w.x, x.x, a1); a1 = fmaf(w.y, x.y, a1);
            a1 = fmaf(w.z, x.z, a1); a1 = fmaf(w.w, x.w, a1);
            x = ((const float4*)As[2])[k4];
            a2 = fmaf(w.x, x.x, a2); a2 = fmaf(w.y, x.y, a2);
            a2 = fmaf(w.z, x.z, a2); a2 = fmaf(w.w, x.w, a2);
            x = ((const float4*)As[3])[k4];
            a3 = fmaf(w.x, x.x, a3); a3 = fmaf(w.y, x.y, a3);
            a3 = fmaf(w.z, x.z, a3); a3 = fmaf(w.w, x.w, a3);
        }
        if (rbase + 0 < n_rows) out[(size_t)(rbase + 0) * EMB + j] = a0;
        if (rbase + 1 < n_rows) out[(size_t)(rbase + 1) * EMB + j] = a1;
        if (rbase + 2 < n_rows) out[(size_t)(rbase + 2) * EMB + j] = a2;
        if (rbase + 3 < n_rows) out[(size_t)(rbase + 3) * EMB + j] = a3;
    }
}

// ---------------------------------------------------------------------------
// Fused edge stage: joint = Lp[s] + Rp[d] + ef*w_edge; t = relu(joint*scale);
// msg = t @ W_final^T + b_final; atomicAdd into g_conv[d].
// 128 threads per block, ETILE=32 edges per block.
// ---------------------------------------------------------------------------
__global__ __launch_bounds__(128) void edge_kernel(
    const void* __restrict__ eidx_raw, const float* __restrict__ ef,
    const float* __restrict__ wedge, const float* __restrict__ Wf,
    const float* __restrict__ bf, const float* __restrict__ scale_p,
    int n_edges)
{
    __shared__ __align__(16) float Ts[ETILE][EMB];
    __shared__ int Dd[ETILE];
    const int e0 = blockIdx.x * ETILE;
    const float scale = scale_p[0];
    const int tid = threadIdx.x;
    const int warp = tid >> 5, lane = tid & 31;
    const int is64 = g_is64;
    const long long* __restrict__ e64 = (const long long*)eidx_raw;
    const int* __restrict__ e32 = (const int*)eidx_raw;

    const float4 we = ((const float4*)wedge)[lane];

    // gather + combine + relu into the shared tile
    for (int e = warp; e < ETILE; e += 4) {
        const int ge = e0 + e;
        float4 t = make_float4(0.f, 0.f, 0.f, 0.f);
        int dd = -1;
        if (ge < n_edges) {
            long long s, d;
            if (is64) { s = e64[ge]; d = e64[n_edges + ge]; }
            else      { s = e32[ge]; d = e32[n_edges + ge]; }
            dd = (int)d;
            const float4 l = ((const float4*)(g_Lp + (size_t)s * EMB))[lane];
            const float4 r = ((const float4*)(g_Rp + (size_t)d * EMB))[lane];
            const float fe = ef[ge];
            t.x = fmaxf(fmaf(fe, we.x, l.x + r.x) * scale, 0.f);
            t.y = fmaxf(fmaf(fe, we.y, l.y + r.y) * scale, 0.f);
            t.z = fmaxf(fmaf(fe, we.z, l.z + r.z) * scale, 0.f);
            t.w = fmaxf(fmaf(fe, we.w, l.w + r.w) * scale, 0.f);
        }
        if (lane == 0) Dd[e] = dd;
        ((float4*)Ts[e])[lane] = t;
    }
    __syncthreads();

    // GEMM: thread j = tid computes msg[e][j] for all 32 edges
    float acc[ETILE];
    const float bj = bf[tid];
#pragma unroll
    for (int e = 0; e < ETILE; e++) acc[e] = bj;
    const float4* __restrict__ Wrow = (const float4*)(Wf + (size_t)tid * EMB);
#pragma unroll 2
    for (int k4 = 0; k4 < 32; k4++) {
        const float4 w = Wrow[k4];
#pragma unroll
        for (int e = 0; e < ETILE; e++) {
            const float4 x = ((const float4*)Ts[e])[k4];  // broadcast LDS
            acc[e] = fmaf(w.x, x.x, acc[e]);
            acc[e] = fmaf(w.y, x.y, acc[e]);
            acc[e] = fmaf(w.z, x.z, acc[e]);
            acc[e] = fmaf(w.w, x.w, acc[e]);
        }
    }

    // scatter-add (coalesced: warp covers 128B of one destination row)
#pragma unroll
    for (int e = 0; e < ETILE; e++) {
        const int d = Dd[e];
        if (d >= 0) atomicAdd(&g_conv[(size_t)d * EMB + tid], acc[e]);
    }
}

// ---------------------------------------------------------------------------
// Output MLP: h = [conv*scale_post ; right];  u = relu(h@W1^T + b1);
// out = u@W2^T + b2.  128 threads, OROWS rows per block.
// ---------------------------------------------------------------------------
__global__ __launch_bounds__(128) void out_kernel(
    const float* __restrict__ right, const float* __restrict__ scale_post_p,
    const float* __restrict__ W1, const float* __restrict__ b1,
    const float* __restrict__ W2, const float* __restrict__ b2,
    float* __restrict__ out, int n_right)
{
    __shared__ __align__(16) float Hs[OROWS][2 * EMB];
    __shared__ __align__(16) float Us[OROWS][EMB];
    const int j = threadIdx.x;
    const int row0 = blockIdx.x * OROWS;
    const float sp = scale_post_p[0];

    for (int i = threadIdx.x; i < OROWS * 64; i += 128) {
        const int r = i >> 6;
        const int c4 = i & 63;
        const int row = row0 + r;
        float4 v = make_float4(0.f, 0.f, 0.f, 0.f);
        if (row < n_right) {
            if (c4 < 32) {
                v = ((const float4*)(g_conv + (size_t)row * EMB))[c4];
                v.x *= sp; v.y *= sp; v.z *= sp; v.w *= sp;
            } else {
                v = ((const float4*)(right + (size_t)row * EMB))[c4 - 32];
            }
        }
        ((float4*)Hs[r])[c4] = v;
    }
    __syncthreads();

    float acc[OROWS];
    const float b1j = b1[j];
#pragma unroll
    for (int r = 0; r < OROWS; r++) acc[r] = b1j;
    const float4* __restrict__ W1r = (const float4*)(W1 + (size_t)j * 2 * EMB);
#pragma unroll 2
    for (int k4 = 0; k4 < 64; k4++) {
        const float4 w = W1r[k4];
#pragma unroll
        for (int r = 0; r < OROWS; r++) {
            const float4 x = ((const float4*)Hs[r])[k4];
            acc[r] = fmaf(w.x, x.x, acc[r]);
            acc[r] = fmaf(w.y, x.y, acc[r]);
            acc[r] = fmaf(w.z, x.z, acc[r]);
            acc[r] = fmaf(w.w, x.w, acc[r]);
        }
    }
#pragma unroll
    for (int r = 0; r < OROWS; r++) Us[r][j] = fmaxf(acc[r], 0.f);
    __syncthreads();

    float acc2[OROWS];
    const float b2j = b2[j];
#pragma unroll
    for (int r = 0; r < OROWS; r++) acc2[r] = b2j;
    const float4* __restrict__ W2r = (const float4*)(W2 + (size_t)j * EMB);
#pragma unroll 2
    for (int k4 = 0; k4 < 32; k4++) {
        const float4 w = W2r[k4];
#pragma unroll
        for (int r = 0; r < OROWS; r++) {
            const float4 x = ((const float4*)Us[r])[k4];
            acc2[r] = fmaf(w.x, x.x, acc2[r]);
            acc2[r] = fmaf(w.y, x.y, acc2[r]);
            acc2[r] = fmaf(w.z, x.z, acc2[r]);
            acc2[r] = fmaf(w.w, x.w, acc2[r]);
        }
    }
#pragma unroll
    for (int r = 0; r < OROWS; r++) {
        const int row = row0 + r;
        if (row < n_right) out[(size_t)row * EMB + j] = acc2[r];
    }
}

// ---------------------------------------------------------------------------
extern "C" void kernel_launch(void* const* d_in, const int* in_sizes, int n_in,
                              void* d_out, int out_size)
{
    const float* left   = (const float*)d_in[0];
    const void*  eidx   = d_in[1];
    const float* ef     = (const float*)d_in[2];
    const float* right  = (const float*)d_in[3];
    // d_in[4] = scatter_out_size scalar (derived from right_features instead)
    const float* W_left      = (const float*)d_in[5];
    const float* b_left      = (const float*)d_in[6];
    const float* W_edge      = (const float*)d_in[7];
    const float* W_right     = (const float*)d_in[8];
    const float* scale_final = (const float*)d_in[9];
    const float* W_final     = (const float*)d_in[10];
    const float* b_final     = (const float*)d_in[11];
    const float* scale_post  = (const float*)d_in[12];
    const float* W_out1      = (const float*)d_in[13];
    const float* b_out1      = (const float*)d_in[14];
    const float* W_out2      = (const float*)d_in[15];
    const float* b_out2      = (const float*)d_in[16];

    const int n_left  = in_sizes[0] / EMB;
    const int n_edges = in_sizes[2];          // edge_features count (EDGE_FEAT=1)
    const int n_right = in_sizes[3] / EMB;

    float *Lp, *Rp;
    cudaGetSymbolAddress((void**)&Lp, g_Lp);
    cudaGetSymbolAddress((void**)&Rp, g_Rp);

    detect_idx_kernel<<<1, 32>>>((const long long*)eidx, n_edges);

    proj_kernel<<<(n_left + 63) / 64, 128>>>(left, W_left, b_left, Lp, n_left);
    proj_kernel<<<(n_right + 63) / 64, 128>>>(right, W_right, nullptr, Rp, n_right);

    const int n4 = n_right * EMB / 4;
    zero_conv_kernel<<<(n4 + 255) / 256, 256>>>(n4);

    edge_kernel<<<(n_edges + ETILE - 1) / ETILE, 128>>>(
        eidx, ef, W_edge, W_final, b_final, scale_final, n_edges);

    out_kernel<<<(n_right + OROWS - 1) / OROWS, 128>>>(
        right, scale_post, W_out1, b_out1, W_out2, b_out2,
        (float*)d_out, n_right);
}